// round 6
// baseline (speedup 1.0000x reference)
#include <cuda_runtime.h>
#include <cuda_bf16.h>
#include <cstdint>

// ---------------------------------------------------------------------------
// Problem constants
// ---------------------------------------------------------------------------
#define NMODES   128
#define TWO_N    256
#define NLAYERS  8
#define BATCH    131072
#define M_TILE   128
#define NTILES   (BATCH / M_TILE)      // 1024
#define GRID_P   148
#define NTHREADS 512

#define S_C  0.70710678118654752440f

// ---------------------------------------------------------------------------
// Shared memory layout: W (hi+lo) 128K, A (hi+lo) 64K
// ---------------------------------------------------------------------------
#define OFF_WH   0
#define OFF_WL   65536
#define OFF_A    131072
#define SMEM_BYTES (OFF_A + 65536)     // 196608

// ---------------------------------------------------------------------------
// Global scratch
// ---------------------------------------------------------------------------
__device__ float          g_S[TWO_N * TWO_N];
__device__ __nv_bfloat16  g_Wh[TWO_N * NMODES];
__device__ __nv_bfloat16  g_Wl[TWO_N * NMODES];
__device__ float          g_c[NMODES];

// ---------------------------------------------------------------------------
// Kernel 1: build S. 32 blocks x 256 threads (8 columns per block).
// Per-(layer,mode) 2x2 blocks computed once per block into smem.
// ---------------------------------------------------------------------------
__device__ __forceinline__ void bs_chain(float t[4], int lane)
{
    const unsigned FULL = 0xffffffffu;
    float lv0 = (lane == 0) ? t[0] : S_C * t[0];
    float lv1 = S_C * (lv0 + t[1]);
    float lv2 = S_C * (lv1 + t[2]);
    float lv3 = S_C * (lv2 + t[3]);
    float carry = lv3;
    float o;
    o = __shfl_up_sync(FULL, carry, 1);  if (lane >= 1)  carry = fmaf(0.25f,                 o, carry);
    o = __shfl_up_sync(FULL, carry, 2);  if (lane >= 2)  carry = fmaf(0.0625f,               o, carry);
    o = __shfl_up_sync(FULL, carry, 4);  if (lane >= 4)  carry = fmaf(0.00390625f,           o, carry);
    o = __shfl_up_sync(FULL, carry, 8);  if (lane >= 8)  carry = fmaf(1.52587890625e-05f,    o, carry);
    o = __shfl_up_sync(FULL, carry, 16); if (lane >= 16) carry = fmaf(2.3283064365386963e-10f, o, carry);
    float exc = __shfl_up_sync(FULL, carry, 1);
    if (lane == 0) exc = 0.f;
    float u0 = fmaf(S_C,                  exc, lv0);
    float u1 = fmaf(0.5f,                 exc, lv1);
    float u2 = fmaf(0.35355339059327373f, exc, lv2);
    float u3 = fmaf(0.25f,                exc, lv3);
    float tn = __shfl_down_sync(FULL, t[0], 1);
    t[0] = S_C * (u0 - t[1]);
    t[1] = S_C * (u1 - t[2]);
    t[2] = S_C * (u2 - t[3]);
    t[3] = (lane == 31) ? u3 : S_C * (u3 - tn);
}

__global__ __launch_bounds__(256) void build_S_kernel(const float* __restrict__ params)
{
    __shared__ float4 sblk[NLAYERS * NMODES];
    int tid = threadIdx.x;
#pragma unroll
    for (int q = 0; q < 4; ++q) {
        int idx = tid + q * 256;                       // 0..1023
        int l = idx >> 7, b = idx & 127;
        float th1 = params[l * (3 * NMODES) + 3 * b + 0];
        float r   = params[l * (3 * NMODES) + 3 * b + 1];
        float th2 = params[l * (3 * NMODES) + 3 * b + 2];
        float s1, c1, s2, c2;
        sincosf(th1, &s1, &c1);
        sincosf(th2, &s2, &c2);
        float em = expf(-r), ep = expf(r);
        float A00 =  em * c1, A01 = -em * s1;
        float A10 =  ep * s1, A11 =  ep * c1;
        sblk[idx] = make_float4(c2 * A00 - s2 * A10,
                                c2 * A01 - s2 * A11,
                                s2 * A00 + c2 * A10,
                                s2 * A01 + c2 * A11);
    }
    __syncthreads();

    int c    = blockIdx.x * 8 + (tid >> 5);
    int lane = tid & 31;
    float x[4], p[4];
#pragma unroll
    for (int j = 0; j < 4; ++j) {
        int b = 4 * lane + j;
        x[j] = (c == 2 * b)     ? 1.f : 0.f;
        p[j] = (c == 2 * b + 1) ? 1.f : 0.f;
    }
    for (int l = 0; l < NLAYERS; ++l) {
#pragma unroll
        for (int j = 0; j < 4; ++j) {
            float4 Bv = sblk[l * NMODES + 4 * lane + j];
            float nx = Bv.x * x[j] + Bv.y * p[j];
            float np = Bv.z * x[j] + Bv.w * p[j];
            x[j] = nx; p[j] = np;
        }
        bs_chain(x, lane);
        bs_chain(p, lane);
    }
#pragma unroll
    for (int j = 0; j < 4; ++j) {
        int b = 4 * lane + j;
        g_S[(2 * b)     * TWO_N + c] = x[j];
        g_S[(2 * b + 1) * TWO_N + c] = p[j];
    }
}

// ---------------------------------------------------------------------------
// Kernel 2: pack W (bf16 hi/lo) and per-mode constants
// ---------------------------------------------------------------------------
__global__ __launch_bounds__(128) void pack_kernel()
{
    int i = blockIdx.x;
    int t = threadIdx.x;
    const float* r0 = g_S + (2 * i)     * TWO_N;
    const float* r1 = g_S + (2 * i + 1) * TWO_N;
    float a0 = r0[t], a1 = r0[t + 128], b0 = r1[t], b1 = r1[t + 128];
    float sq = a0 * a0 + a1 * a1 + b0 * b0 + b1 * b1;
    __shared__ float red[128];
    red[t] = sq;
    __syncthreads();
    for (int off = 64; off > 0; off >>= 1) {
        if (t < off) red[t] += red[t + off];
        __syncthreads();
    }
    if (t == 0) g_c[i] = red[0] * 0.25f - 0.5f;

    float w0 = r0[2 * t];
    float w1 = r1[2 * t];
    __nv_bfloat16 h0 = __float2bfloat16(w0);
    __nv_bfloat16 h1 = __float2bfloat16(w1);
    g_Wh[(2 * i)     * NMODES + t] = h0;
    g_Wh[(2 * i + 1) * NMODES + t] = h1;
    g_Wl[(2 * i)     * NMODES + t] = __float2bfloat16(w0 - __bfloat162float(h0));
    g_Wl[(2 * i + 1) * NMODES + t] = __float2bfloat16(w1 - __bfloat162float(h1));
}

// ---------------------------------------------------------------------------
// Kernel 3: persistent HMMA GEMM, 512 threads, warp tile m32 x n64.
// ks-outer / pass-inner loop with operand fragment reuse:
//   per ks: {Ah, Wh, Wl} -> 32 MMAs (passes xh*wh + xh*wl), then a second
//   ks loop: {Al, Wh} -> 16 MMAs (pass xl*wh). All accumulate into acc.
// W rows N-permuted in smem so the epilogue is dense STG.128 from registers.
// ---------------------------------------------------------------------------
__device__ __forceinline__ void ldsm_x4(unsigned addr, unsigned& r0, unsigned& r1,
                                        unsigned& r2, unsigned& r3)
{
    asm volatile("ldmatrix.sync.aligned.m8n8.x4.shared.b16 {%0,%1,%2,%3}, [%4];"
                 : "=r"(r0), "=r"(r1), "=r"(r2), "=r"(r3) : "r"(addr));
}
__device__ __forceinline__ void mma_bf16(float* d, const unsigned* a,
                                         unsigned b0, unsigned b1)
{
    asm volatile("mma.sync.aligned.m16n8k16.row.col.f32.bf16.bf16.f32 "
                 "{%0,%1,%2,%3}, {%4,%5,%6,%7}, {%8,%9}, {%0,%1,%2,%3};"
                 : "+f"(d[0]), "+f"(d[1]), "+f"(d[2]), "+f"(d[3])
                 : "r"(a[0]), "r"(a[1]), "r"(a[2]), "r"(a[3]), "r"(b0), "r"(b1));
}

__device__ __forceinline__ void load_A(float4 pf[8], const float* __restrict__ x,
                                       int tile, int tid)
{
    size_t m0 = (size_t)tile * M_TILE;
#pragma unroll
    for (int it = 0; it < 4; ++it) {
        int idx = tid + it * NTHREADS;
        int rr = idx >> 4, cc = idx & 15;
        const float4* g = (const float4*)(x + (m0 + rr) * NMODES + cc * 8);
        pf[2 * it]     = __ldg(g);
        pf[2 * it + 1] = __ldg(g + 1);
    }
}

// hi = truncate-to-bf16 (PRMT), lo = f - hi (exact), packed via cvt.bf16x2
__device__ __forceinline__ void convert_A(char* smem, const float4 pf[8], int tid)
{
#pragma unroll
    for (int it = 0; it < 4; ++it) {
        int idx = tid + it * NTHREADS;
        int rr = idx >> 4, cc = idx & 15;
        float vs[8] = {pf[2*it].x, pf[2*it].y, pf[2*it].z, pf[2*it].w,
                       pf[2*it+1].x, pf[2*it+1].y, pf[2*it+1].z, pf[2*it+1].w};
        unsigned h[4], l[4];
#pragma unroll
        for (int k = 0; k < 4; ++k) {
            float f0 = vs[2 * k], f1 = vs[2 * k + 1];
            unsigned u0 = __float_as_uint(f0), u1 = __float_as_uint(f1);
            h[k] = __byte_perm(u0, u1, 0x7632);
            float lo0 = f0 - __uint_as_float(u0 & 0xffff0000u);
            float lo1 = f1 - __uint_as_float(u1 & 0xffff0000u);
            asm("cvt.rn.bf16x2.f32 %0, %1, %2;" : "=r"(l[k]) : "f"(lo1), "f"(lo0));
        }
        unsigned off = rr * 256 + ((cc ^ (rr & 7)) << 4);
        *(uint4*)(smem + OFF_A + off)         = make_uint4(h[0], h[1], h[2], h[3]);
        *(uint4*)(smem + OFF_A + 32768 + off) = make_uint4(l[0], l[1], l[2], l[3]);
    }
}

__global__ __launch_bounds__(NTHREADS, 1) void gemm_kernel(const float* __restrict__ x,
                                                           float* __restrict__ out)
{
    extern __shared__ char smem[];
    const unsigned sbase = (unsigned)__cvta_generic_to_shared(smem);
    int tid = threadIdx.x, lane = tid & 31, wid = tid >> 5;
    int wm = wid & 3;          // 4 m-groups x 32 rows
    int wn = wid >> 2;         // 4 n-groups x 64 y-cols (32 modes)

    // ---- Stage W (hi+lo) with N-permutation, swizzled 256B rows ----
#pragma unroll
    for (int it = 0; it < 16; ++it) {
        int idx = tid + it * NTHREADS;               // 0..8191 units of 16B
        int arr = idx >> 12;
        int rr  = (idx >> 4) & 255;
        int cc  = idx & 15;
        int p   = rr & 63;
        int nt  = p >> 3, c = (p >> 1) & 3, par = p & 1;
        int ml  = c * 4 + (nt & 3) + ((nt >> 2) << 4);
        int j   = (rr & ~63) + 2 * ml + par;
        uint4 v = *(const uint4*)((arr ? g_Wl : g_Wh) + j * NMODES + cc * 8);
        *(uint4*)(smem + (arr ? OFF_WL : OFF_WH) + rr * 256 + ((cc ^ (rr & 7)) << 4)) = v;
    }

    float cvals[8];
#pragma unroll
    for (int nt = 0; nt < 8; ++nt)
        cvals[nt] = __ldg(&g_c[wn * 32 + (lane & 3) * 4 + (nt & 3) + ((nt >> 2) << 4)]);

    // ldsm lane mappings
    int a_row = (lane & 15);
    int a_cc  = (lane >> 4);
    int b_row = ((lane >> 4) << 3) + (lane & 7);
    int b_cc  = ((lane >> 3) & 1);

    // precomputed swizzled base addresses (k advances by +32B per ks, swizzle
    // XOR only touches bits inside the 256B row so we add 32*ks separately;
    // careful: swizzle depends on cc which includes ks -> recompute per ks)
    const unsigned AhB = sbase + OFF_A;
    const unsigned AlB = sbase + OFF_A + 32768;
    const unsigned WhB = sbase + OFF_WH;
    const unsigned WlB = sbase + OFF_WL;

    // ---- prologue ----
    int t = blockIdx.x;
    float4 pf[8];
    load_A(pf, x, t, tid);
    convert_A(smem, pf, tid);
    if (t + GRID_P < NTILES) load_A(pf, x, t + GRID_P, tid);
    __syncthreads();

    while (t < NTILES) {
        float acc[2][8][4];
#pragma unroll
        for (int mf = 0; mf < 2; ++mf)
#pragma unroll
            for (int nt = 0; nt < 8; ++nt)
#pragma unroll
                for (int q = 0; q < 4; ++q) acc[mf][nt][q] = 0.f;

        // ---- phase 1: Ah x (Wh, Wl): 10 ldsm, 32 MMA per ks ----
#pragma unroll
        for (int ks = 0; ks < 8; ++ks) {
            unsigned af[2][4];
#pragma unroll
            for (int mf = 0; mf < 2; ++mf) {
                int ar = wm * 32 + mf * 16 + a_row;
                int cc = 2 * ks + a_cc;
                ldsm_x4(AhB + ar * 256 + ((cc ^ (ar & 7)) << 4),
                        af[mf][0], af[mf][1], af[mf][2], af[mf][3]);
            }
            unsigned bh[4][4], bl[4][4];
#pragma unroll
            for (int p = 0; p < 4; ++p) {
                int br = wn * 64 + p * 16 + b_row;
                int cc = 2 * ks + b_cc;
                unsigned soff = br * 256 + ((cc ^ (br & 7)) << 4);
                ldsm_x4(WhB + soff, bh[p][0], bh[p][1], bh[p][2], bh[p][3]);
                ldsm_x4(WlB + soff, bl[p][0], bl[p][1], bl[p][2], bl[p][3]);
            }
#pragma unroll
            for (int p = 0; p < 4; ++p) {
                mma_bf16(acc[0][2*p],   af[0], bh[p][0], bh[p][1]);
                mma_bf16(acc[1][2*p],   af[1], bh[p][0], bh[p][1]);
                mma_bf16(acc[0][2*p+1], af[0], bh[p][2], bh[p][3]);
                mma_bf16(acc[1][2*p+1], af[1], bh[p][2], bh[p][3]);
                mma_bf16(acc[0][2*p],   af[0], bl[p][0], bl[p][1]);
                mma_bf16(acc[1][2*p],   af[1], bl[p][0], bl[p][1]);
                mma_bf16(acc[0][2*p+1], af[0], bl[p][2], bl[p][3]);
                mma_bf16(acc[1][2*p+1], af[1], bl[p][2], bl[p][3]);
            }
        }

        // ---- phase 2: Al x Wh: 6 ldsm, 16 MMA per ks ----
#pragma unroll
        for (int ks = 0; ks < 8; ++ks) {
            unsigned af[2][4];
#pragma unroll
            for (int mf = 0; mf < 2; ++mf) {
                int ar = wm * 32 + mf * 16 + a_row;
                int cc = 2 * ks + a_cc;
                ldsm_x4(AlB + ar * 256 + ((cc ^ (ar & 7)) << 4),
                        af[mf][0], af[mf][1], af[mf][2], af[mf][3]);
            }
            unsigned bh[4][4];
#pragma unroll
            for (int p = 0; p < 4; ++p) {
                int br = wn * 64 + p * 16 + b_row;
                int cc = 2 * ks + b_cc;
                unsigned soff = br * 256 + ((cc ^ (br & 7)) << 4);
                ldsm_x4(WhB + soff, bh[p][0], bh[p][1], bh[p][2], bh[p][3]);
            }
#pragma unroll
            for (int p = 0; p < 4; ++p) {
                mma_bf16(acc[0][2*p],   af[0], bh[p][0], bh[p][1]);
                mma_bf16(acc[1][2*p],   af[1], bh[p][0], bh[p][1]);
                mma_bf16(acc[0][2*p+1], af[0], bh[p][2], bh[p][3]);
                mma_bf16(acc[1][2*p+1], af[1], bh[p][2], bh[p][3]);
            }
        }

        __syncthreads();                      // A smem reads done

        // ---- convert next tile into A smem, prefetch tile after ----
        bool have_next = (t + GRID_P < NTILES);
        if (have_next) {
            convert_A(smem, pf, tid);
            if (t + 2 * GRID_P < NTILES) load_A(pf, x, t + 2 * GRID_P, tid);
        }
        __syncthreads();                      // A smem ready for next MMA

        // ---- epilogue (overlaps other warps' next-tile MMA) ----
        {
            size_t m0 = (size_t)t * M_TILE;
            int mode0 = wn * 32 + (lane & 3) * 4;
#pragma unroll
            for (int mf = 0; mf < 2; ++mf) {
#pragma unroll
                for (int h = 0; h < 2; ++h) {
                    int row = wm * 32 + mf * 16 + (lane >> 2) + h * 8;
                    float* o = out + (m0 + row) * NMODES + mode0;
                    float v[8];
#pragma unroll
                    for (int nt = 0; nt < 8; ++nt) {
                        float f0 = acc[mf][nt][2 * h];
                        float f1 = acc[mf][nt][2 * h + 1];
                        v[nt] = fmaf(f0, f0, fmaf(f1, f1, cvals[nt]));
                    }
                    *(float4*)(o)      = make_float4(v[0], v[1], v[2], v[3]);
                    *(float4*)(o + 16) = make_float4(v[4], v[5], v[6], v[7]);
                }
            }
        }

        t += GRID_P;
    }
}

// ---------------------------------------------------------------------------
// Launch
// ---------------------------------------------------------------------------
extern "C" void kernel_launch(void* const* d_in, const int* in_sizes, int n_in,
                              void* d_out, int out_size)
{
    const float* inputs = (const float*)d_in[0];
    const float* params = (const float*)d_in[1];
    float* out = (float*)d_out;

    cudaFuncSetAttribute(gemm_kernel, cudaFuncAttributeMaxDynamicSharedMemorySize,
                         SMEM_BYTES);

    build_S_kernel<<<32, 256>>>(params);
    pack_kernel<<<NMODES, 128>>>();
    gemm_kernel<<<GRID_P, NTHREADS, SMEM_BYTES>>>(inputs, out);
}

// round 7
// speedup vs baseline: 1.0152x; 1.0152x over previous
#include <cuda_runtime.h>
#include <cuda_bf16.h>
#include <cstdint>

// ---------------------------------------------------------------------------
// Problem constants
// ---------------------------------------------------------------------------
#define NMODES   128
#define TWO_N    256
#define NLAYERS  8
#define BATCH    131072
#define M_TILE   128
#define NTILES   (BATCH / M_TILE)      // 1024
#define GRID_P   148
#define NTHREADS 512

#define S_C  0.70710678118654752440f

// ---------------------------------------------------------------------------
// Shared memory: Wh 64K | Wl 64K | Al 32K | Ah[2] 64K  = 224K
// ---------------------------------------------------------------------------
#define OFF_WH   0
#define OFF_WL   65536
#define OFF_AL   131072
#define OFF_AH   163840
#define SMEM_BYTES (OFF_AH + 2 * 32768)   // 229376

// ---------------------------------------------------------------------------
// Global scratch
// ---------------------------------------------------------------------------
__device__ float          g_S[TWO_N * TWO_N];
__device__ __nv_bfloat16  g_Wh[TWO_N * NMODES];
__device__ __nv_bfloat16  g_Wl[TWO_N * NMODES];
__device__ float          g_c[NMODES];

// ---------------------------------------------------------------------------
// Kernel 1: build S. 32 blocks x 256 threads (8 columns per block).
// Fast-math intrinsics (MUFU) — slow-path sincosf was 10us of runtime.
// ---------------------------------------------------------------------------
__device__ __forceinline__ void bs_chain(float t[4], int lane)
{
    const unsigned FULL = 0xffffffffu;
    float lv0 = (lane == 0) ? t[0] : S_C * t[0];
    float lv1 = S_C * (lv0 + t[1]);
    float lv2 = S_C * (lv1 + t[2]);
    float lv3 = S_C * (lv2 + t[3]);
    float carry = lv3;
    float o;
    o = __shfl_up_sync(FULL, carry, 1);  if (lane >= 1)  carry = fmaf(0.25f,                 o, carry);
    o = __shfl_up_sync(FULL, carry, 2);  if (lane >= 2)  carry = fmaf(0.0625f,               o, carry);
    o = __shfl_up_sync(FULL, carry, 4);  if (lane >= 4)  carry = fmaf(0.00390625f,           o, carry);
    o = __shfl_up_sync(FULL, carry, 8);  if (lane >= 8)  carry = fmaf(1.52587890625e-05f,    o, carry);
    o = __shfl_up_sync(FULL, carry, 16); if (lane >= 16) carry = fmaf(2.3283064365386963e-10f, o, carry);
    float exc = __shfl_up_sync(FULL, carry, 1);
    if (lane == 0) exc = 0.f;
    float u0 = fmaf(S_C,                  exc, lv0);
    float u1 = fmaf(0.5f,                 exc, lv1);
    float u2 = fmaf(0.35355339059327373f, exc, lv2);
    float u3 = fmaf(0.25f,                exc, lv3);
    float tn = __shfl_down_sync(FULL, t[0], 1);
    t[0] = S_C * (u0 - t[1]);
    t[1] = S_C * (u1 - t[2]);
    t[2] = S_C * (u2 - t[3]);
    t[3] = (lane == 31) ? u3 : S_C * (u3 - tn);
}

__global__ __launch_bounds__(256) void build_S_kernel(const float* __restrict__ params)
{
    __shared__ float4 sblk[NLAYERS * NMODES];
    int tid = threadIdx.x;
#pragma unroll
    for (int q = 0; q < 4; ++q) {
        int idx = tid + q * 256;
        int l = idx >> 7, b = idx & 127;
        float th1 = params[l * (3 * NMODES) + 3 * b + 0];
        float r   = params[l * (3 * NMODES) + 3 * b + 1];
        float th2 = params[l * (3 * NMODES) + 3 * b + 2];
        float s1, c1, s2, c2;
        __sincosf(th1, &s1, &c1);
        __sincosf(th2, &s2, &c2);
        float em = __expf(-r), ep = __expf(r);
        float A00 =  em * c1, A01 = -em * s1;
        float A10 =  ep * s1, A11 =  ep * c1;
        sblk[idx] = make_float4(c2 * A00 - s2 * A10,
                                c2 * A01 - s2 * A11,
                                s2 * A00 + c2 * A10,
                                s2 * A01 + c2 * A11);
    }
    __syncthreads();

    int c    = blockIdx.x * 8 + (tid >> 5);
    int lane = tid & 31;
    float x[4], p[4];
#pragma unroll
    for (int j = 0; j < 4; ++j) {
        int b = 4 * lane + j;
        x[j] = (c == 2 * b)     ? 1.f : 0.f;
        p[j] = (c == 2 * b + 1) ? 1.f : 0.f;
    }
    for (int l = 0; l < NLAYERS; ++l) {
#pragma unroll
        for (int j = 0; j < 4; ++j) {
            float4 Bv = sblk[l * NMODES + 4 * lane + j];
            float nx = Bv.x * x[j] + Bv.y * p[j];
            float np = Bv.z * x[j] + Bv.w * p[j];
            x[j] = nx; p[j] = np;
        }
        bs_chain(x, lane);
        bs_chain(p, lane);
    }
#pragma unroll
    for (int j = 0; j < 4; ++j) {
        int b = 4 * lane + j;
        g_S[(2 * b)     * TWO_N + c] = x[j];
        g_S[(2 * b + 1) * TWO_N + c] = p[j];
    }
}

// ---------------------------------------------------------------------------
// Kernel 2: pack W (bf16 hi/lo) and per-mode constants
// ---------------------------------------------------------------------------
__global__ __launch_bounds__(128) void pack_kernel()
{
    int i = blockIdx.x;
    int t = threadIdx.x;
    const float* r0 = g_S + (2 * i)     * TWO_N;
    const float* r1 = g_S + (2 * i + 1) * TWO_N;
    float a0 = r0[t], a1 = r0[t + 128], b0 = r1[t], b1 = r1[t + 128];
    float sq = a0 * a0 + a1 * a1 + b0 * b0 + b1 * b1;
    __shared__ float red[128];
    red[t] = sq;
    __syncthreads();
    for (int off = 64; off > 0; off >>= 1) {
        if (t < off) red[t] += red[t + off];
        __syncthreads();
    }
    if (t == 0) g_c[i] = red[0] * 0.25f - 0.5f;

    float w0 = r0[2 * t];
    float w1 = r1[2 * t];
    __nv_bfloat16 h0 = __float2bfloat16(w0);
    __nv_bfloat16 h1 = __float2bfloat16(w1);
    g_Wh[(2 * i)     * NMODES + t] = h0;
    g_Wh[(2 * i + 1) * NMODES + t] = h1;
    g_Wl[(2 * i)     * NMODES + t] = __float2bfloat16(w0 - __bfloat162float(h0));
    g_Wl[(2 * i + 1) * NMODES + t] = __float2bfloat16(w1 - __bfloat162float(h1));
}

// ---------------------------------------------------------------------------
// Kernel 3: persistent HMMA GEMM, 512 threads, warp tile m32 x n64.
// Per-tile schedule (phase2 first):
//   phase2: Al[t] x Wh            (16 MMA/ks)
//   bar1
//   convert both hi/lo of tile t+1 (Al single-buf, Ah double-buf)
//   phase1: Ah[t] x Wh then x Wl  (32 MMA/ks; absorbs convert issue slots)
//   bar2
//   epilogue STGs for t; LDG prefetch t+2
// ---------------------------------------------------------------------------
__device__ __forceinline__ void ldsm_x4(unsigned addr, unsigned& r0, unsigned& r1,
                                        unsigned& r2, unsigned& r3)
{
    asm volatile("ldmatrix.sync.aligned.m8n8.x4.shared.b16 {%0,%1,%2,%3}, [%4];"
                 : "=r"(r0), "=r"(r1), "=r"(r2), "=r"(r3) : "r"(addr));
}
__device__ __forceinline__ void mma_bf16(float* d, const unsigned* a,
                                         unsigned b0, unsigned b1)
{
    asm volatile("mma.sync.aligned.m16n8k16.row.col.f32.bf16.bf16.f32 "
                 "{%0,%1,%2,%3}, {%4,%5,%6,%7}, {%8,%9}, {%0,%1,%2,%3};"
                 : "+f"(d[0]), "+f"(d[1]), "+f"(d[2]), "+f"(d[3])
                 : "r"(a[0]), "r"(a[1]), "r"(a[2]), "r"(a[3]), "r"(b0), "r"(b1));
}

__device__ __forceinline__ void load_A(float4 pf[8], const float* __restrict__ x,
                                       int tile, int tid)
{
    size_t m0 = (size_t)tile * M_TILE;
#pragma unroll
    for (int it = 0; it < 4; ++it) {
        int idx = tid + it * NTHREADS;
        int rr = idx >> 4, cc = idx & 15;
        const float4* g = (const float4*)(x + (m0 + rr) * NMODES + cc * 8);
        pf[2 * it]     = __ldg(g);
        pf[2 * it + 1] = __ldg(g + 1);
    }
}

// hi = truncate-to-bf16 (PRMT), lo = f - hi (exact) packed via cvt.rn.bf16x2
__device__ __forceinline__ void convert_A2(char* smem, unsigned offAh,
                                           const float4 pf[8], int tid)
{
#pragma unroll
    for (int it = 0; it < 4; ++it) {
        int idx = tid + it * NTHREADS;
        int rr = idx >> 4, cc = idx & 15;
        float vs[8] = {pf[2*it].x, pf[2*it].y, pf[2*it].z, pf[2*it].w,
                       pf[2*it+1].x, pf[2*it+1].y, pf[2*it+1].z, pf[2*it+1].w};
        unsigned h[4], l[4];
#pragma unroll
        for (int k = 0; k < 4; ++k) {
            float f0 = vs[2 * k], f1 = vs[2 * k + 1];
            unsigned u0 = __float_as_uint(f0), u1 = __float_as_uint(f1);
            h[k] = __byte_perm(u0, u1, 0x7632);
            float lo0 = f0 - __uint_as_float(u0 & 0xffff0000u);
            float lo1 = f1 - __uint_as_float(u1 & 0xffff0000u);
            asm("cvt.rn.bf16x2.f32 %0, %1, %2;" : "=r"(l[k]) : "f"(lo1), "f"(lo0));
        }
        unsigned off = rr * 256 + ((cc ^ (rr & 7)) << 4);
        *(uint4*)(smem + offAh + off)   = make_uint4(h[0], h[1], h[2], h[3]);
        *(uint4*)(smem + OFF_AL + off)  = make_uint4(l[0], l[1], l[2], l[3]);
    }
}

__global__ __launch_bounds__(NTHREADS, 1) void gemm_kernel(const float* __restrict__ x,
                                                           float* __restrict__ out)
{
    extern __shared__ char smem[];
    const unsigned sbase = (unsigned)__cvta_generic_to_shared(smem);
    int tid = threadIdx.x, lane = tid & 31, wid = tid >> 5;
    int wm = wid & 3;          // 4 m-groups x 32 rows
    int wn = wid >> 2;         // 4 n-groups x 64 y-cols (32 modes)

    // ---- Stage W (hi+lo) with N-permutation, swizzled 256B rows ----
#pragma unroll
    for (int it = 0; it < 16; ++it) {
        int idx = tid + it * NTHREADS;
        int arr = idx >> 12;
        int rr  = (idx >> 4) & 255;
        int cc  = idx & 15;
        int p   = rr & 63;
        int nt  = p >> 3, c = (p >> 1) & 3, par = p & 1;
        int ml  = c * 4 + (nt & 3) + ((nt >> 2) << 4);
        int j   = (rr & ~63) + 2 * ml + par;
        uint4 v = *(const uint4*)((arr ? g_Wl : g_Wh) + j * NMODES + cc * 8);
        *(uint4*)(smem + (arr ? OFF_WL : OFF_WH) + rr * 256 + ((cc ^ (rr & 7)) << 4)) = v;
    }

    float cvals[8];
#pragma unroll
    for (int nt = 0; nt < 8; ++nt)
        cvals[nt] = __ldg(&g_c[wn * 32 + (lane & 3) * 4 + (nt & 3) + ((nt >> 2) << 4)]);

    // ldsm lane mappings
    int a_row = (lane & 15);
    int a_cc  = (lane >> 4);
    int b_row = ((lane >> 4) << 3) + (lane & 7);
    int b_cc  = ((lane >> 3) & 1);

    const unsigned AlB = sbase + OFF_AL;
    const unsigned WhB = sbase + OFF_WH;
    const unsigned WlB = sbase + OFF_WL;

    // ---- prologue ----
    int t = blockIdx.x;
    float4 pf[8];
    load_A(pf, x, t, tid);
    convert_A2(smem, OFF_AH, pf, tid);                 // tile t -> Al, Ah[0]
    if (t + GRID_P < NTILES) load_A(pf, x, t + GRID_P, tid);
    __syncthreads();

    int buf = 0;
    while (t < NTILES) {
        float acc[2][8][4];
#pragma unroll
        for (int mf = 0; mf < 2; ++mf)
#pragma unroll
            for (int nt = 0; nt < 8; ++nt)
#pragma unroll
                for (int q = 0; q < 4; ++q) acc[mf][nt][q] = 0.f;

        // ---- phase2: Al x Wh (16 MMA per ks) ----
#pragma unroll
        for (int ks = 0; ks < 8; ++ks) {
            unsigned af[2][4];
#pragma unroll
            for (int mf = 0; mf < 2; ++mf) {
                int ar = wm * 32 + mf * 16 + a_row;
                int cc = 2 * ks + a_cc;
                ldsm_x4(AlB + ar * 256 + ((cc ^ (ar & 7)) << 4),
                        af[mf][0], af[mf][1], af[mf][2], af[mf][3]);
            }
            unsigned bh[4][4];
#pragma unroll
            for (int p = 0; p < 4; ++p) {
                int br = wn * 64 + p * 16 + b_row;
                int cc = 2 * ks + b_cc;
                ldsm_x4(WhB + br * 256 + ((cc ^ (br & 7)) << 4),
                        bh[p][0], bh[p][1], bh[p][2], bh[p][3]);
            }
#pragma unroll
            for (int p = 0; p < 4; ++p) {
                mma_bf16(acc[0][2*p],   af[0], bh[p][0], bh[p][1]);
                mma_bf16(acc[1][2*p],   af[1], bh[p][0], bh[p][1]);
                mma_bf16(acc[0][2*p+1], af[0], bh[p][2], bh[p][3]);
                mma_bf16(acc[1][2*p+1], af[1], bh[p][2], bh[p][3]);
            }
        }
        __syncthreads();                      // bar1: Al reads done

        // ---- convert tile t+1 (Al + other Ah buffer); absorbed by phase1 ----
        bool n1 = (t + GRID_P < NTILES);
        if (n1) convert_A2(smem, OFF_AH + (buf ^ 1) * 32768, pf, tid);

        // ---- phase1: Ah[buf] x Wh then x Wl (32 MMA per ks) ----
        unsigned AhB = sbase + OFF_AH + buf * 32768;
#pragma unroll
        for (int ks = 0; ks < 8; ++ks) {
            unsigned af[2][4];
#pragma unroll
            for (int mf = 0; mf < 2; ++mf) {
                int ar = wm * 32 + mf * 16 + a_row;
                int cc = 2 * ks + a_cc;
                ldsm_x4(AhB + ar * 256 + ((cc ^ (ar & 7)) << 4),
                        af[mf][0], af[mf][1], af[mf][2], af[mf][3]);
            }
            unsigned bb[4][4];
#pragma unroll
            for (int p = 0; p < 4; ++p) {
                int br = wn * 64 + p * 16 + b_row;
                int cc = 2 * ks + b_cc;
                ldsm_x4(WhB + br * 256 + ((cc ^ (br & 7)) << 4),
                        bb[p][0], bb[p][1], bb[p][2], bb[p][3]);
            }
#pragma unroll
            for (int p = 0; p < 4; ++p) {
                mma_bf16(acc[0][2*p],   af[0], bb[p][0], bb[p][1]);
                mma_bf16(acc[1][2*p],   af[1], bb[p][0], bb[p][1]);
                mma_bf16(acc[0][2*p+1], af[0], bb[p][2], bb[p][3]);
                mma_bf16(acc[1][2*p+1], af[1], bb[p][2], bb[p][3]);
            }
#pragma unroll
            for (int p = 0; p < 4; ++p) {
                int br = wn * 64 + p * 16 + b_row;
                int cc = 2 * ks + b_cc;
                ldsm_x4(WlB + br * 256 + ((cc ^ (br & 7)) << 4),
                        bb[p][0], bb[p][1], bb[p][2], bb[p][3]);
            }
#pragma unroll
            for (int p = 0; p < 4; ++p) {
                mma_bf16(acc[0][2*p],   af[0], bb[p][0], bb[p][1]);
                mma_bf16(acc[1][2*p],   af[1], bb[p][0], bb[p][1]);
                mma_bf16(acc[0][2*p+1], af[0], bb[p][2], bb[p][3]);
                mma_bf16(acc[1][2*p+1], af[1], bb[p][2], bb[p][3]);
            }
        }
        __syncthreads();                      // bar2: Ah reads done

        // ---- epilogue: dense STG.128 from registers ----
        {
            size_t m0 = (size_t)t * M_TILE;
            int mode0 = wn * 32 + (lane & 3) * 4;
#pragma unroll
            for (int mf = 0; mf < 2; ++mf) {
#pragma unroll
                for (int h = 0; h < 2; ++h) {
                    int row = wm * 32 + mf * 16 + (lane >> 2) + h * 8;
                    float* o = out + (m0 + row) * NMODES + mode0;
                    float v[8];
#pragma unroll
                    for (int nt = 0; nt < 8; ++nt) {
                        float f0 = acc[mf][nt][2 * h];
                        float f1 = acc[mf][nt][2 * h + 1];
                        v[nt] = fmaf(f0, f0, fmaf(f1, f1, cvals[nt]));
                    }
                    *(float4*)(o)      = make_float4(v[0], v[1], v[2], v[3]);
                    *(float4*)(o + 16) = make_float4(v[4], v[5], v[6], v[7]);
                }
            }
        }

        // ---- prefetch tile t+2G ----
        if (t + 2 * GRID_P < NTILES) load_A(pf, x, t + 2 * GRID_P, tid);

        t += GRID_P;
        buf ^= 1;
    }
}

// ---------------------------------------------------------------------------
// Launch
// ---------------------------------------------------------------------------
extern "C" void kernel_launch(void* const* d_in, const int* in_sizes, int n_in,
                              void* d_out, int out_size)
{
    const float* inputs = (const float*)d_in[0];
    const float* params = (const float*)d_in[1];
    float* out = (float*)d_out;

    cudaFuncSetAttribute(gemm_kernel, cudaFuncAttributeMaxDynamicSharedMemorySize,
                         SMEM_BYTES);

    build_S_kernel<<<32, 256>>>(params);
    pack_kernel<<<NMODES, 128>>>();
    gemm_kernel<<<GRID_P, NTHREADS, SMEM_BYTES>>>(inputs, out);
}

// round 8
// speedup vs baseline: 1.0382x; 1.0227x over previous
#include <cuda_runtime.h>
#include <cuda_bf16.h>
#include <cstdint>

// ---------------------------------------------------------------------------
// Problem constants
// ---------------------------------------------------------------------------
#define NMODES   128
#define TWO_N    256
#define NLAYERS  8
#define BATCH    131072
#define M_TILE   64
#define NTILES_M (BATCH / M_TILE)      // 2048
#define GRID_P   296                   // 2 CTAs per SM, split-N
#define STRIDE_T 148
#define NTHREADS 256

#define S_C  0.70710678118654752440f

// ---------------------------------------------------------------------------
// Shared memory per CTA: Wh 32K | Wl 32K | Al 16K | Ah[2] 32K = 112K
// ---------------------------------------------------------------------------
#define OFF_WH   0
#define OFF_WL   32768
#define OFF_AL   65536
#define OFF_AH   81920
#define SMEM_BYTES (OFF_AH + 2 * 16384)   // 114688

// ---------------------------------------------------------------------------
// Global scratch
// ---------------------------------------------------------------------------
__device__ float          g_S[TWO_N * TWO_N];
__device__ __nv_bfloat16  g_Wh[TWO_N * NMODES];
__device__ __nv_bfloat16  g_Wl[TWO_N * NMODES];
__device__ float          g_c[NMODES];

// ---------------------------------------------------------------------------
// Kernel 1: build S. x/p scans interleaved for 2x ILP on the shfl chain.
// ---------------------------------------------------------------------------
__device__ __forceinline__ void bs_chain2(float x[4], float p[4], int lane)
{
    const unsigned FULL = 0xffffffffu;
    float xl0 = (lane == 0) ? x[0] : S_C * x[0];
    float pl0 = (lane == 0) ? p[0] : S_C * p[0];
    float xl1 = S_C * (xl0 + x[1]);
    float pl1 = S_C * (pl0 + p[1]);
    float xl2 = S_C * (xl1 + x[2]);
    float pl2 = S_C * (pl1 + p[2]);
    float xl3 = S_C * (xl2 + x[3]);
    float pl3 = S_C * (pl2 + p[3]);
    float xc = xl3, pc = pl3;
    float ox, op;
    ox = __shfl_up_sync(FULL, xc, 1);  op = __shfl_up_sync(FULL, pc, 1);
    if (lane >= 1)  { xc = fmaf(0.25f, ox, xc);                  pc = fmaf(0.25f, op, pc); }
    ox = __shfl_up_sync(FULL, xc, 2);  op = __shfl_up_sync(FULL, pc, 2);
    if (lane >= 2)  { xc = fmaf(0.0625f, ox, xc);                pc = fmaf(0.0625f, op, pc); }
    ox = __shfl_up_sync(FULL, xc, 4);  op = __shfl_up_sync(FULL, pc, 4);
    if (lane >= 4)  { xc = fmaf(0.00390625f, ox, xc);            pc = fmaf(0.00390625f, op, pc); }
    ox = __shfl_up_sync(FULL, xc, 8);  op = __shfl_up_sync(FULL, pc, 8);
    if (lane >= 8)  { xc = fmaf(1.52587890625e-05f, ox, xc);     pc = fmaf(1.52587890625e-05f, op, pc); }
    ox = __shfl_up_sync(FULL, xc, 16); op = __shfl_up_sync(FULL, pc, 16);
    if (lane >= 16) { xc = fmaf(2.3283064365386963e-10f, ox, xc); pc = fmaf(2.3283064365386963e-10f, op, pc); }
    float xe = __shfl_up_sync(FULL, xc, 1);
    float pe = __shfl_up_sync(FULL, pc, 1);
    if (lane == 0) { xe = 0.f; pe = 0.f; }
    float xu0 = fmaf(S_C, xe, xl0),                  pu0 = fmaf(S_C, pe, pl0);
    float xu1 = fmaf(0.5f, xe, xl1),                 pu1 = fmaf(0.5f, pe, pl1);
    float xu2 = fmaf(0.35355339059327373f, xe, xl2), pu2 = fmaf(0.35355339059327373f, pe, pl2);
    float xu3 = fmaf(0.25f, xe, xl3),                pu3 = fmaf(0.25f, pe, pl3);
    float xtn = __shfl_down_sync(FULL, x[0], 1);
    float ptn = __shfl_down_sync(FULL, p[0], 1);
    x[0] = S_C * (xu0 - x[1]);   p[0] = S_C * (pu0 - p[1]);
    x[1] = S_C * (xu1 - x[2]);   p[1] = S_C * (pu1 - p[2]);
    x[2] = S_C * (xu2 - x[3]);   p[2] = S_C * (pu2 - p[3]);
    x[3] = (lane == 31) ? xu3 : S_C * (xu3 - xtn);
    p[3] = (lane == 31) ? pu3 : S_C * (pu3 - ptn);
}

__global__ __launch_bounds__(256) void build_S_kernel(const float* __restrict__ params)
{
    __shared__ float4 sblk[NLAYERS * NMODES];
    int tid = threadIdx.x;
#pragma unroll
    for (int q = 0; q < 4; ++q) {
        int idx = tid + q * 256;
        int l = idx >> 7, b = idx & 127;
        float th1 = params[l * (3 * NMODES) + 3 * b + 0];
        float r   = params[l * (3 * NMODES) + 3 * b + 1];
        float th2 = params[l * (3 * NMODES) + 3 * b + 2];
        float s1, c1, s2, c2;
        __sincosf(th1, &s1, &c1);
        __sincosf(th2, &s2, &c2);
        float em = __expf(-r), ep = __expf(r);
        float A00 =  em * c1, A01 = -em * s1;
        float A10 =  ep * s1, A11 =  ep * c1;
        sblk[idx] = make_float4(c2 * A00 - s2 * A10,
                                c2 * A01 - s2 * A11,
                                s2 * A00 + c2 * A10,
                                s2 * A01 + c2 * A11);
    }
    __syncthreads();

    int c    = blockIdx.x * 8 + (tid >> 5);
    int lane = tid & 31;
    float x[4], p[4];
#pragma unroll
    for (int j = 0; j < 4; ++j) {
        int b = 4 * lane + j;
        x[j] = (c == 2 * b)     ? 1.f : 0.f;
        p[j] = (c == 2 * b + 1) ? 1.f : 0.f;
    }
    for (int l = 0; l < NLAYERS; ++l) {
#pragma unroll
        for (int j = 0; j < 4; ++j) {
            float4 Bv = sblk[l * NMODES + 4 * lane + j];
            float nx = Bv.x * x[j] + Bv.y * p[j];
            float np = Bv.z * x[j] + Bv.w * p[j];
            x[j] = nx; p[j] = np;
        }
        bs_chain2(x, p, lane);
    }
#pragma unroll
    for (int j = 0; j < 4; ++j) {
        int b = 4 * lane + j;
        g_S[(2 * b)     * TWO_N + c] = x[j];
        g_S[(2 * b + 1) * TWO_N + c] = p[j];
    }
}

// ---------------------------------------------------------------------------
// Kernel 2: pack W (bf16 hi/lo) and per-mode constants
// ---------------------------------------------------------------------------
__global__ __launch_bounds__(128) void pack_kernel()
{
    int i = blockIdx.x;
    int t = threadIdx.x;
    const float* r0 = g_S + (2 * i)     * TWO_N;
    const float* r1 = g_S + (2 * i + 1) * TWO_N;
    float a0 = r0[t], a1 = r0[t + 128], b0 = r1[t], b1 = r1[t + 128];
    float sq = a0 * a0 + a1 * a1 + b0 * b0 + b1 * b1;
    __shared__ float red[128];
    red[t] = sq;
    __syncthreads();
    for (int off = 64; off > 0; off >>= 1) {
        if (t < off) red[t] += red[t + off];
        __syncthreads();
    }
    if (t == 0) g_c[i] = red[0] * 0.25f - 0.5f;

    float w0 = r0[2 * t];
    float w1 = r1[2 * t];
    __nv_bfloat16 h0 = __float2bfloat16(w0);
    __nv_bfloat16 h1 = __float2bfloat16(w1);
    g_Wh[(2 * i)     * NMODES + t] = h0;
    g_Wh[(2 * i + 1) * NMODES + t] = h1;
    g_Wl[(2 * i)     * NMODES + t] = __float2bfloat16(w0 - __bfloat162float(h0));
    g_Wl[(2 * i + 1) * NMODES + t] = __float2bfloat16(w1 - __bfloat162float(h1));
}

// ---------------------------------------------------------------------------
// Kernel 3: persistent HMMA GEMM, 2 CTAs/SM (split-N), 256 thr, warp m32xn32.
// CTA parity q owns modes [q*64, q*64+64) i.e. W rows [q*128, (q+1)*128).
// The two co-resident CTAs are unsynchronized -> each hides the other's
// barrier/convert/epilogue windows.
// ---------------------------------------------------------------------------
__device__ __forceinline__ void ldsm_x4(unsigned addr, unsigned& r0, unsigned& r1,
                                        unsigned& r2, unsigned& r3)
{
    asm volatile("ldmatrix.sync.aligned.m8n8.x4.shared.b16 {%0,%1,%2,%3}, [%4];"
                 : "=r"(r0), "=r"(r1), "=r"(r2), "=r"(r3) : "r"(addr));
}
__device__ __forceinline__ void mma_bf16(float* d, const unsigned* a,
                                         unsigned b0, unsigned b1)
{
    asm volatile("mma.sync.aligned.m16n8k16.row.col.f32.bf16.bf16.f32 "
                 "{%0,%1,%2,%3}, {%4,%5,%6,%7}, {%8,%9}, {%0,%1,%2,%3};"
                 : "+f"(d[0]), "+f"(d[1]), "+f"(d[2]), "+f"(d[3])
                 : "r"(a[0]), "r"(a[1]), "r"(a[2]), "r"(a[3]), "r"(b0), "r"(b1));
}

__device__ __forceinline__ void load_A(float4 pf[8], const float* __restrict__ x,
                                       int tile, int tid)
{
    size_t m0 = (size_t)tile * M_TILE;
#pragma unroll
    for (int it = 0; it < 4; ++it) {
        int idx = tid + it * NTHREADS;            // 0..1023
        int rr = idx >> 4, cc = idx & 15;
        const float4* g = (const float4*)(x + (m0 + rr) * NMODES + cc * 8);
        pf[2 * it]     = __ldg(g);
        pf[2 * it + 1] = __ldg(g + 1);
    }
}

// hi = truncate-to-bf16 (PRMT), lo = f - hi (exact) packed via cvt.rn.bf16x2
__device__ __forceinline__ void convert_A2(char* smem, unsigned offAh,
                                           const float4 pf[8], int tid)
{
#pragma unroll
    for (int it = 0; it < 4; ++it) {
        int idx = tid + it * NTHREADS;
        int rr = idx >> 4, cc = idx & 15;
        float vs[8] = {pf[2*it].x, pf[2*it].y, pf[2*it].z, pf[2*it].w,
                       pf[2*it+1].x, pf[2*it+1].y, pf[2*it+1].z, pf[2*it+1].w};
        unsigned h[4], l[4];
#pragma unroll
        for (int k = 0; k < 4; ++k) {
            float f0 = vs[2 * k], f1 = vs[2 * k + 1];
            unsigned u0 = __float_as_uint(f0), u1 = __float_as_uint(f1);
            h[k] = __byte_perm(u0, u1, 0x7632);
            float lo0 = f0 - __uint_as_float(u0 & 0xffff0000u);
            float lo1 = f1 - __uint_as_float(u1 & 0xffff0000u);
            asm("cvt.rn.bf16x2.f32 %0, %1, %2;" : "=r"(l[k]) : "f"(lo1), "f"(lo0));
        }
        unsigned off = rr * 256 + ((cc ^ (rr & 7)) << 4);
        *(uint4*)(smem + offAh + off)   = make_uint4(h[0], h[1], h[2], h[3]);
        *(uint4*)(smem + OFF_AL + off)  = make_uint4(l[0], l[1], l[2], l[3]);
    }
}

__global__ __launch_bounds__(NTHREADS, 2) void gemm_kernel(const float* __restrict__ x,
                                                           float* __restrict__ out)
{
    extern __shared__ char smem[];
    const unsigned sbase = (unsigned)__cvta_generic_to_shared(smem);
    int tid = threadIdx.x, lane = tid & 31, wid = tid >> 5;
    int wm = wid & 1;          // 2 m-groups x 32 rows
    int wn = wid >> 1;         // 4 n-groups x 32 smem rows (16 modes each)
    const int q = blockIdx.x & 1;               // N-half of this CTA

    // ---- Stage this half's W (hi+lo) with N-permutation, swizzled ----
#pragma unroll
    for (int it = 0; it < 16; ++it) {
        int idx = tid + it * NTHREADS;           // 0..4095 units of 16B
        int arr = idx >> 11;
        int rem = idx & 2047;
        int rr  = rem >> 4;                      // smem row 0..127
        int cc  = idx & 15;
        int g   = rr >> 5, p = rr & 31;
        int ntj = p >> 3, c = (p >> 1) & 3, par = p & 1;
        int ml  = c * 4 + ntj;                   // 0..15 within group
        int j   = q * 128 + g * 32 + 2 * ml + par;
        uint4 v = *(const uint4*)((arr ? g_Wl : g_Wh) + j * NMODES + cc * 8);
        *(uint4*)(smem + (arr ? OFF_WL : OFF_WH) + rr * 256 + ((cc ^ (rr & 7)) << 4)) = v;
    }

    float cvals[4];
#pragma unroll
    for (int j = 0; j < 4; ++j)
        cvals[j] = __ldg(&g_c[q * 64 + wn * 16 + (lane & 3) * 4 + j]);

    // ldsm lane mappings
    int a_row = (lane & 15);
    int a_cc  = (lane >> 4);
    int b_row = ((lane >> 4) << 3) + (lane & 7);
    int b_cc  = ((lane >> 3) & 1);

    const unsigned AlB = sbase + OFF_AL;
    const unsigned WhB = sbase + OFF_WH;
    const unsigned WlB = sbase + OFF_WL;

    // ---- prologue ----
    int t = blockIdx.x >> 1;                     // 0..147
    float4 pf[8];
    load_A(pf, x, t, tid);
    convert_A2(smem, OFF_AH, pf, tid);
    if (t + STRIDE_T < NTILES_M) load_A(pf, x, t + STRIDE_T, tid);
    __syncthreads();

    int buf = 0;
    while (t < NTILES_M) {
        float acc[2][4][4];
#pragma unroll
        for (int mf = 0; mf < 2; ++mf)
#pragma unroll
            for (int j = 0; j < 4; ++j)
#pragma unroll
                for (int v = 0; v < 4; ++v) acc[mf][j][v] = 0.f;

        // ---- phase2: Al x Wh (8 MMA per ks) ----
#pragma unroll
        for (int ks = 0; ks < 8; ++ks) {
            unsigned af[2][4];
#pragma unroll
            for (int mf = 0; mf < 2; ++mf) {
                int ar = wm * 32 + mf * 16 + a_row;
                int cc = 2 * ks + a_cc;
                ldsm_x4(AlB + ar * 256 + ((cc ^ (ar & 7)) << 4),
                        af[mf][0], af[mf][1], af[mf][2], af[mf][3]);
            }
            unsigned bh[2][4];
#pragma unroll
            for (int p = 0; p < 2; ++p) {
                int br = wn * 32 + p * 16 + b_row;
                int cc = 2 * ks + b_cc;
                ldsm_x4(WhB + br * 256 + ((cc ^ (br & 7)) << 4),
                        bh[p][0], bh[p][1], bh[p][2], bh[p][3]);
            }
#pragma unroll
            for (int p = 0; p < 2; ++p) {
                mma_bf16(acc[0][2*p],   af[0], bh[p][0], bh[p][1]);
                mma_bf16(acc[1][2*p],   af[1], bh[p][0], bh[p][1]);
                mma_bf16(acc[0][2*p+1], af[0], bh[p][2], bh[p][3]);
                mma_bf16(acc[1][2*p+1], af[1], bh[p][2], bh[p][3]);
            }
        }
        __syncthreads();                      // Al reads done

        // ---- convert tile t+1 into Al + other Ah buffer ----
        if (t + STRIDE_T < NTILES_M)
            convert_A2(smem, OFF_AH + (buf ^ 1) * 16384, pf, tid);

        // ---- phase1: Ah[buf] x Wh then x Wl (16 MMA per ks) ----
        unsigned AhB = sbase + OFF_AH + buf * 16384;
#pragma unroll
        for (int ks = 0; ks < 8; ++ks) {
            unsigned af[2][4];
#pragma unroll
            for (int mf = 0; mf < 2; ++mf) {
                int ar = wm * 32 + mf * 16 + a_row;
                int cc = 2 * ks + a_cc;
                ldsm_x4(AhB + ar * 256 + ((cc ^ (ar & 7)) << 4),
                        af[mf][0], af[mf][1], af[mf][2], af[mf][3]);
            }
            unsigned bb[2][4];
#pragma unroll
            for (int p = 0; p < 2; ++p) {
                int br = wn * 32 + p * 16 + b_row;
                int cc = 2 * ks + b_cc;
                ldsm_x4(WhB + br * 256 + ((cc ^ (br & 7)) << 4),
                        bb[p][0], bb[p][1], bb[p][2], bb[p][3]);
            }
#pragma unroll
            for (int p = 0; p < 2; ++p) {
                mma_bf16(acc[0][2*p],   af[0], bb[p][0], bb[p][1]);
                mma_bf16(acc[1][2*p],   af[1], bb[p][0], bb[p][1]);
                mma_bf16(acc[0][2*p+1], af[0], bb[p][2], bb[p][3]);
                mma_bf16(acc[1][2*p+1], af[1], bb[p][2], bb[p][3]);
            }
#pragma unroll
            for (int p = 0; p < 2; ++p) {
                int br = wn * 32 + p * 16 + b_row;
                int cc = 2 * ks + b_cc;
                ldsm_x4(WlB + br * 256 + ((cc ^ (br & 7)) << 4),
                        bb[p][0], bb[p][1], bb[p][2], bb[p][3]);
            }
#pragma unroll
            for (int p = 0; p < 2; ++p) {
                mma_bf16(acc[0][2*p],   af[0], bb[p][0], bb[p][1]);
                mma_bf16(acc[1][2*p],   af[1], bb[p][0], bb[p][1]);
                mma_bf16(acc[0][2*p+1], af[0], bb[p][2], bb[p][3]);
                mma_bf16(acc[1][2*p+1], af[1], bb[p][2], bb[p][3]);
            }
        }
        __syncthreads();                      // Ah reads done

        // ---- epilogue: dense STG.128 from registers ----
        {
            size_t m0 = (size_t)t * M_TILE;
            int mode0 = q * 64 + wn * 16 + (lane & 3) * 4;
#pragma unroll
            for (int mf = 0; mf < 2; ++mf) {
#pragma unroll
                for (int h = 0; h < 2; ++h) {
                    int row = wm * 32 + mf * 16 + (lane >> 2) + h * 8;
                    float* o = out + (m0 + row) * NMODES + mode0;
                    float v[4];
#pragma unroll
                    for (int j = 0; j < 4; ++j) {
                        float f0 = acc[mf][j][2 * h];
                        float f1 = acc[mf][j][2 * h + 1];
                        v[j] = fmaf(f0, f0, fmaf(f1, f1, cvals[j]));
                    }
                    *(float4*)o = make_float4(v[0], v[1], v[2], v[3]);
                }
            }
        }

        // ---- prefetch tile t+2*stride ----
        if (t + 2 * STRIDE_T < NTILES_M) load_A(pf, x, t + 2 * STRIDE_T, tid);

        t += STRIDE_T;
        buf ^= 1;
    }
}

// ---------------------------------------------------------------------------
// Launch
// ---------------------------------------------------------------------------
extern "C" void kernel_launch(void* const* d_in, const int* in_sizes, int n_in,
                              void* d_out, int out_size)
{
    const float* inputs = (const float*)d_in[0];
    const float* params = (const float*)d_in[1];
    float* out = (float*)d_out;

    cudaFuncSetAttribute(gemm_kernel, cudaFuncAttributeMaxDynamicSharedMemorySize,
                         SMEM_BYTES);

    build_S_kernel<<<32, 256>>>(params);
    pack_kernel<<<NMODES, 128>>>();
    gemm_kernel<<<GRID_P, NTHREADS, SMEM_BYTES>>>(inputs, out);
}

// round 9
// speedup vs baseline: 1.4828x; 1.4282x over previous
#include <cuda_runtime.h>
#include <cuda_fp16.h>
#include <cstdint>

// ---------------------------------------------------------------------------
// Problem constants
// ---------------------------------------------------------------------------
#define NMODES   128
#define TWO_N    256
#define NLAYERS  8
#define BATCH    131072
#define M_TILE   64
#define NTILES_M (BATCH / M_TILE)      // 2048
#define GRID_P   296                   // 2 CTAs per SM, split-N
#define STRIDE_T 148
#define NTHREADS 256

#define S_C  0.70710678118654752440f
#define WSCALE 0.0625f                 // W stored * 1/16 (fp16 range safety)
#define WSCALE_INV 16.0f

// ---------------------------------------------------------------------------
// Shared memory per CTA: Wh 32K | Wl 32K | A[2] 32K = 96K
// ---------------------------------------------------------------------------
#define OFF_WH   0
#define OFF_WL   32768
#define OFF_A    65536
#define SMEM_BYTES (OFF_A + 2 * 16384)   // 98304

// ---------------------------------------------------------------------------
// Global scratch
// ---------------------------------------------------------------------------
__device__ float  g_S[TWO_N * TWO_N];
__device__ __half g_Wh[TWO_N * NMODES];
__device__ __half g_Wl[TWO_N * NMODES];
__device__ float  g_c[NMODES];

// ---------------------------------------------------------------------------
// Kernel 1: build S. Branchless masked-coefficient scan (no BSSY regions),
// x/p chains interleaved for ILP.
// ---------------------------------------------------------------------------
__device__ __forceinline__ void bs_chain2(float x[4], float p[4],
                                          float a0, float c1m, float c2m,
                                          float c4m, float c8m, float c16m,
                                          float e0, float s31, float m31)
{
    const unsigned FULL = 0xffffffffu;
    float xl0 = a0 * x[0];
    float pl0 = a0 * p[0];
    float xl1 = S_C * (xl0 + x[1]);
    float pl1 = S_C * (pl0 + p[1]);
    float xl2 = S_C * (xl1 + x[2]);
    float pl2 = S_C * (pl1 + p[2]);
    float xl3 = S_C * (xl2 + x[3]);
    float pl3 = S_C * (pl2 + p[3]);
    float xc = xl3, pc = pl3;
    xc = fmaf(c1m,  __shfl_up_sync(FULL, xc, 1),  xc);
    pc = fmaf(c1m,  __shfl_up_sync(FULL, pc, 1),  pc);
    xc = fmaf(c2m,  __shfl_up_sync(FULL, xc, 2),  xc);
    pc = fmaf(c2m,  __shfl_up_sync(FULL, pc, 2),  pc);
    xc = fmaf(c4m,  __shfl_up_sync(FULL, xc, 4),  xc);
    pc = fmaf(c4m,  __shfl_up_sync(FULL, pc, 4),  pc);
    xc = fmaf(c8m,  __shfl_up_sync(FULL, xc, 8),  xc);
    pc = fmaf(c8m,  __shfl_up_sync(FULL, pc, 8),  pc);
    xc = fmaf(c16m, __shfl_up_sync(FULL, xc, 16), xc);
    pc = fmaf(c16m, __shfl_up_sync(FULL, pc, 16), pc);
    float xe = e0 * __shfl_up_sync(FULL, xc, 1);
    float pe = e0 * __shfl_up_sync(FULL, pc, 1);
    float xu0 = fmaf(S_C, xe, xl0),                  pu0 = fmaf(S_C, pe, pl0);
    float xu1 = fmaf(0.5f, xe, xl1),                 pu1 = fmaf(0.5f, pe, pl1);
    float xu2 = fmaf(0.35355339059327373f, xe, xl2), pu2 = fmaf(0.35355339059327373f, pe, pl2);
    float xu3 = fmaf(0.25f, xe, xl3),                pu3 = fmaf(0.25f, pe, pl3);
    float xtn = __shfl_down_sync(FULL, x[0], 1);
    float ptn = __shfl_down_sync(FULL, p[0], 1);
    x[0] = S_C * (xu0 - x[1]);   p[0] = S_C * (pu0 - p[1]);
    x[1] = S_C * (xu1 - x[2]);   p[1] = S_C * (pu1 - p[2]);
    x[2] = S_C * (xu2 - x[3]);   p[2] = S_C * (pu2 - p[3]);
    x[3] = s31 * (xu3 - m31 * xtn);
    p[3] = s31 * (pu3 - m31 * ptn);
}

__global__ __launch_bounds__(256) void build_S_kernel(const float* __restrict__ params)
{
    __shared__ float4 sblk[NLAYERS * NMODES];
    int tid = threadIdx.x;
#pragma unroll
    for (int q = 0; q < 4; ++q) {
        int idx = tid + q * 256;
        int l = idx >> 7, b = idx & 127;
        float th1 = params[l * (3 * NMODES) + 3 * b + 0];
        float r   = params[l * (3 * NMODES) + 3 * b + 1];
        float th2 = params[l * (3 * NMODES) + 3 * b + 2];
        float s1, c1, s2, c2;
        __sincosf(th1, &s1, &c1);
        __sincosf(th2, &s2, &c2);
        float em = __expf(-r), ep = __expf(r);
        float A00 =  em * c1, A01 = -em * s1;
        float A10 =  ep * s1, A11 =  ep * c1;
        sblk[idx] = make_float4(c2 * A00 - s2 * A10,
                                c2 * A01 - s2 * A11,
                                s2 * A00 + c2 * A10,
                                s2 * A01 + c2 * A11);
    }
    __syncthreads();

    int c    = blockIdx.x * 8 + (tid >> 5);
    int lane = tid & 31;

    // precomputed branchless masks/coefficients
    float a0   = (lane == 0)  ? 1.f : S_C;
    float c1m  = (lane >= 1)  ? 0.25f : 0.f;
    float c2m  = (lane >= 2)  ? 0.0625f : 0.f;
    float c4m  = (lane >= 4)  ? 0.00390625f : 0.f;
    float c8m  = (lane >= 8)  ? 1.52587890625e-05f : 0.f;
    float c16m = (lane >= 16) ? 2.3283064365386963e-10f : 0.f;
    float e0   = (lane == 0)  ? 0.f : 1.f;
    float s31  = (lane == 31) ? 1.f : S_C;
    float m31  = (lane == 31) ? 0.f : 1.f;

    float x[4], p[4];
#pragma unroll
    for (int j = 0; j < 4; ++j) {
        int b = 4 * lane + j;
        x[j] = (c == 2 * b)     ? 1.f : 0.f;
        p[j] = (c == 2 * b + 1) ? 1.f : 0.f;
    }
    for (int l = 0; l < NLAYERS; ++l) {
#pragma unroll
        for (int j = 0; j < 4; ++j) {
            float4 Bv = sblk[l * NMODES + 4 * lane + j];
            float nx = Bv.x * x[j] + Bv.y * p[j];
            float np = Bv.z * x[j] + Bv.w * p[j];
            x[j] = nx; p[j] = np;
        }
        bs_chain2(x, p, a0, c1m, c2m, c4m, c8m, c16m, e0, s31, m31);
    }
#pragma unroll
    for (int j = 0; j < 4; ++j) {
        int b = 4 * lane + j;
        g_S[(2 * b)     * TWO_N + c] = x[j];
        g_S[(2 * b + 1) * TWO_N + c] = p[j];
    }
}

// ---------------------------------------------------------------------------
// Kernel 2: pack W (fp16 hi/lo, scaled by 1/16) and per-mode constants
// ---------------------------------------------------------------------------
__global__ __launch_bounds__(128) void pack_kernel()
{
    int i = blockIdx.x;
    int t = threadIdx.x;
    const float* r0 = g_S + (2 * i)     * TWO_N;
    const float* r1 = g_S + (2 * i + 1) * TWO_N;
    float a0 = r0[t], a1 = r0[t + 128], b0 = r1[t], b1 = r1[t + 128];
    float sq = a0 * a0 + a1 * a1 + b0 * b0 + b1 * b1;
    __shared__ float red[128];
    red[t] = sq;
    __syncthreads();
    for (int off = 64; off > 0; off >>= 1) {
        if (t < off) red[t] += red[t + off];
        __syncthreads();
    }
    if (t == 0) g_c[i] = red[0] * 0.25f - 0.5f;

    float w0 = r0[2 * t] * WSCALE;
    float w1 = r1[2 * t] * WSCALE;
    __half h0 = __float2half_rn(w0);
    __half h1 = __float2half_rn(w1);
    g_Wh[(2 * i)     * NMODES + t] = h0;
    g_Wh[(2 * i + 1) * NMODES + t] = h1;
    g_Wl[(2 * i)     * NMODES + t] = __float2half_rn(w0 - __half2float(h0));
    g_Wl[(2 * i + 1) * NMODES + t] = __float2half_rn(w1 - __half2float(h1));
}

// ---------------------------------------------------------------------------
// Kernel 3: persistent fp16 HMMA GEMM, 2 CTAs/SM (split-N), 256 threads.
// 2-pass: y = xf*Wh + xf*Wl (same A fragments feed both passes).
// One barrier per tile; A double-buffered.
// ---------------------------------------------------------------------------
__device__ __forceinline__ void ldsm_x4(unsigned addr, unsigned& r0, unsigned& r1,
                                        unsigned& r2, unsigned& r3)
{
    asm volatile("ldmatrix.sync.aligned.m8n8.x4.shared.b16 {%0,%1,%2,%3}, [%4];"
                 : "=r"(r0), "=r"(r1), "=r"(r2), "=r"(r3) : "r"(addr));
}
__device__ __forceinline__ void mma_f16(float* d, const unsigned* a,
                                        unsigned b0, unsigned b1)
{
    asm volatile("mma.sync.aligned.m16n8k16.row.col.f32.f16.f16.f32 "
                 "{%0,%1,%2,%3}, {%4,%5,%6,%7}, {%8,%9}, {%0,%1,%2,%3};"
                 : "+f"(d[0]), "+f"(d[1]), "+f"(d[2]), "+f"(d[3])
                 : "r"(a[0]), "r"(a[1]), "r"(a[2]), "r"(a[3]), "r"(b0), "r"(b1));
}

__device__ __forceinline__ void load_A(float4 pf[8], const float* __restrict__ x,
                                       int tile, int tid)
{
    size_t m0 = (size_t)tile * M_TILE;
#pragma unroll
    for (int it = 0; it < 4; ++it) {
        int idx = tid + it * NTHREADS;            // 0..1023
        int rr = idx >> 4, cc = idx & 15;
        const float4* g = (const float4*)(x + (m0 + rr) * NMODES + cc * 8);
        pf[2 * it]     = __ldg(g);
        pf[2 * it + 1] = __ldg(g + 1);
    }
}

// fp32 -> fp16x2 pack (single-pass A)
__device__ __forceinline__ void convert_A(char* smem, unsigned offA,
                                          const float4 pf[8], int tid)
{
#pragma unroll
    for (int it = 0; it < 4; ++it) {
        int idx = tid + it * NTHREADS;
        int rr = idx >> 4, cc = idx & 15;
        float vs[8] = {pf[2*it].x, pf[2*it].y, pf[2*it].z, pf[2*it].w,
                       pf[2*it+1].x, pf[2*it+1].y, pf[2*it+1].z, pf[2*it+1].w};
        unsigned h[4];
#pragma unroll
        for (int k = 0; k < 4; ++k)
            asm("cvt.rn.f16x2.f32 %0, %1, %2;"
                : "=r"(h[k]) : "f"(vs[2 * k + 1]), "f"(vs[2 * k]));
        unsigned off = rr * 256 + ((cc ^ (rr & 7)) << 4);
        *(uint4*)(smem + offA + off) = make_uint4(h[0], h[1], h[2], h[3]);
    }
}

__global__ __launch_bounds__(NTHREADS, 2) void gemm_kernel(const float* __restrict__ x,
                                                           float* __restrict__ out)
{
    extern __shared__ char smem[];
    const unsigned sbase = (unsigned)__cvta_generic_to_shared(smem);
    int tid = threadIdx.x, lane = tid & 31, wid = tid >> 5;
    int wm = wid & 1;          // 2 m-groups x 32 rows
    int wn = wid >> 1;         // 4 n-groups x 32 smem rows (16 modes each)
    const int q = blockIdx.x & 1;               // N-half of this CTA

    // ---- Stage this half's W (hi+lo) with N-permutation, swizzled ----
#pragma unroll
    for (int it = 0; it < 16; ++it) {
        int idx = tid + it * NTHREADS;           // 0..4095 units of 16B
        int arr = idx >> 11;
        int rem = idx & 2047;
        int rr  = rem >> 4;                      // smem row 0..127
        int cc  = idx & 15;
        int g   = rr >> 5, p = rr & 31;
        int ntj = p >> 3, c = (p >> 1) & 3, par = p & 1;
        int ml  = c * 4 + ntj;
        int j   = q * 128 + g * 32 + 2 * ml + par;
        uint4 v = *(const uint4*)((arr ? g_Wl : g_Wh) + j * NMODES + cc * 8);
        *(uint4*)(smem + (arr ? OFF_WL : OFF_WH) + rr * 256 + ((cc ^ (rr & 7)) << 4)) = v;
    }

    float cvals[4];
#pragma unroll
    for (int j = 0; j < 4; ++j)
        cvals[j] = __ldg(&g_c[q * 64 + wn * 16 + (lane & 3) * 4 + j]);

    // ldsm lane mappings
    int a_row = (lane & 15);
    int a_cc  = (lane >> 4);
    int b_row = ((lane >> 4) << 3) + (lane & 7);
    int b_cc  = ((lane >> 3) & 1);

    const unsigned WhB = sbase + OFF_WH;
    const unsigned WlB = sbase + OFF_WL;

    // ---- prologue ----
    int t = blockIdx.x >> 1;
    float4 pf[8];
    load_A(pf, x, t, tid);
    convert_A(smem, OFF_A, pf, tid);
    if (t + STRIDE_T < NTILES_M) load_A(pf, x, t + STRIDE_T, tid);
    __syncthreads();

    int buf = 0;
    while (t < NTILES_M) {
        float acc[2][4][4];
#pragma unroll
        for (int mf = 0; mf < 2; ++mf)
#pragma unroll
            for (int j = 0; j < 4; ++j)
#pragma unroll
                for (int v = 0; v < 4; ++v) acc[mf][j][v] = 0.f;

        unsigned AB = sbase + OFF_A + buf * 16384;
#pragma unroll
        for (int ks = 0; ks < 8; ++ks) {
            unsigned af[2][4];
#pragma unroll
            for (int mf = 0; mf < 2; ++mf) {
                int ar = wm * 32 + mf * 16 + a_row;
                int cc = 2 * ks + a_cc;
                ldsm_x4(AB + ar * 256 + ((cc ^ (ar & 7)) << 4),
                        af[mf][0], af[mf][1], af[mf][2], af[mf][3]);
            }
            unsigned bh[2][4], bl[2][4];
#pragma unroll
            for (int p = 0; p < 2; ++p) {
                int br = wn * 32 + p * 16 + b_row;
                int cc = 2 * ks + b_cc;
                unsigned soff = br * 256 + ((cc ^ (br & 7)) << 4);
                ldsm_x4(WhB + soff, bh[p][0], bh[p][1], bh[p][2], bh[p][3]);
                ldsm_x4(WlB + soff, bl[p][0], bl[p][1], bl[p][2], bl[p][3]);
            }
#pragma unroll
            for (int p = 0; p < 2; ++p) {
                mma_f16(acc[0][2*p],   af[0], bh[p][0], bh[p][1]);
                mma_f16(acc[1][2*p],   af[1], bh[p][0], bh[p][1]);
                mma_f16(acc[0][2*p+1], af[0], bh[p][2], bh[p][3]);
                mma_f16(acc[1][2*p+1], af[1], bh[p][2], bh[p][3]);
            }
#pragma unroll
            for (int p = 0; p < 2; ++p) {
                mma_f16(acc[0][2*p],   af[0], bl[p][0], bl[p][1]);
                mma_f16(acc[1][2*p],   af[1], bl[p][0], bl[p][1]);
                mma_f16(acc[0][2*p+1], af[0], bl[p][2], bl[p][3]);
                mma_f16(acc[1][2*p+1], af[1], bl[p][2], bl[p][3]);
            }
        }

        // ---- convert next tile into other A buffer (disjoint; no barrier) ----
        if (t + STRIDE_T < NTILES_M)
            convert_A(smem, OFF_A + (buf ^ 1) * 16384, pf, tid);

        // ---- epilogue: dense STG.128 from registers (undo 1/16 W scale) ----
        {
            size_t m0 = (size_t)t * M_TILE;
            int mode0 = q * 64 + wn * 16 + (lane & 3) * 4;
#pragma unroll
            for (int mf = 0; mf < 2; ++mf) {
#pragma unroll
                for (int h = 0; h < 2; ++h) {
                    int row = wm * 32 + mf * 16 + (lane >> 2) + h * 8;
                    float* o = out + (m0 + row) * NMODES + mode0;
                    float v[4];
#pragma unroll
                    for (int j = 0; j < 4; ++j) {
                        float f0 = acc[mf][j][2 * h]     * WSCALE_INV;
                        float f1 = acc[mf][j][2 * h + 1] * WSCALE_INV;
                        v[j] = fmaf(f0, f0, fmaf(f1, f1, cvals[j]));
                    }
                    *(float4*)o = make_float4(v[0], v[1], v[2], v[3]);
                }
            }
        }

        // ---- prefetch tile t+2*stride ----
        if (t + 2 * STRIDE_T < NTILES_M) load_A(pf, x, t + 2 * STRIDE_T, tid);

        __syncthreads();           // converts visible before next MMA loop
        t += STRIDE_T;
        buf ^= 1;
    }
}

// ---------------------------------------------------------------------------
// Launch
// ---------------------------------------------------------------------------
extern "C" void kernel_launch(void* const* d_in, const int* in_sizes, int n_in,
                              void* d_out, int out_size)
{
    const float* inputs = (const float*)d_in[0];
    const float* params = (const float*)d_in[1];
    float* out = (float*)d_out;

    cudaFuncSetAttribute(gemm_kernel, cudaFuncAttributeMaxDynamicSharedMemorySize,
                         SMEM_BYTES);

    build_S_kernel<<<32, 256>>>(params);
    pack_kernel<<<NMODES, 128>>>();
    gemm_kernel<<<GRID_P, NTHREADS, SMEM_BYTES>>>(inputs, out);
}

// round 10
// speedup vs baseline: 1.4889x; 1.0041x over previous
#include <cuda_runtime.h>
#include <cuda_fp16.h>
#include <cstdint>

// ---------------------------------------------------------------------------
// Problem constants
// ---------------------------------------------------------------------------
#define NMODES   128
#define TWO_N    256
#define NLAYERS  8
#define BATCH    131072
#define M_TILE   64
#define NTILES_M (BATCH / M_TILE)      // 2048
#define GRID_P   296                   // 2 CTAs per SM, split-N; one wave
#define STRIDE_T 148
#define NTHREADS 256

#define S_C  0.70710678118654752440f
#define WSCALE 0.0625f                 // W stored * 1/16 (fp16 range safety)
#define WSCALE_INV 16.0f

// ---------------------------------------------------------------------------
// Shared memory per CTA: Wh 32K | Wl 32K | A[2] 32K = 96K
// (build phase reuses the A region for sblk/wpart scratch)
// ---------------------------------------------------------------------------
#define OFF_WH   0
#define OFF_WL   32768
#define OFF_A    65536
#define SMEM_BYTES (OFF_A + 2 * 16384)   // 98304

// ---------------------------------------------------------------------------
// Global scratch
// ---------------------------------------------------------------------------
__device__ __half    g_Wh[TWO_N * NMODES];
__device__ __half    g_Wl[TWO_N * NMODES];
__device__ float     g_part[32 * NMODES];   // per-build-CTA row-square partials
__device__ unsigned  g_bar;                 // epoch grid barrier (never reset)

// ---------------------------------------------------------------------------
// Beamsplitter chain: branchless masked-coefficient warp scan, x/p interleaved
// ---------------------------------------------------------------------------
__device__ __forceinline__ void bs_chain2(float x[4], float p[4],
                                          float a0, float c1m, float c2m,
                                          float c4m, float c8m, float c16m,
                                          float e0, float s31, float m31)
{
    const unsigned FULL = 0xffffffffu;
    float xl0 = a0 * x[0];
    float pl0 = a0 * p[0];
    float xl1 = S_C * (xl0 + x[1]);
    float pl1 = S_C * (pl0 + p[1]);
    float xl2 = S_C * (xl1 + x[2]);
    float pl2 = S_C * (pl1 + p[2]);
    float xl3 = S_C * (xl2 + x[3]);
    float pl3 = S_C * (pl2 + p[3]);
    float xc = xl3, pc = pl3;
    xc = fmaf(c1m,  __shfl_up_sync(FULL, xc, 1),  xc);
    pc = fmaf(c1m,  __shfl_up_sync(FULL, pc, 1),  pc);
    xc = fmaf(c2m,  __shfl_up_sync(FULL, xc, 2),  xc);
    pc = fmaf(c2m,  __shfl_up_sync(FULL, pc, 2),  pc);
    xc = fmaf(c4m,  __shfl_up_sync(FULL, xc, 4),  xc);
    pc = fmaf(c4m,  __shfl_up_sync(FULL, pc, 4),  pc);
    xc = fmaf(c8m,  __shfl_up_sync(FULL, xc, 8),  xc);
    pc = fmaf(c8m,  __shfl_up_sync(FULL, pc, 8),  pc);
    xc = fmaf(c16m, __shfl_up_sync(FULL, xc, 16), xc);
    pc = fmaf(c16m, __shfl_up_sync(FULL, pc, 16), pc);
    float xe = e0 * __shfl_up_sync(FULL, xc, 1);
    float pe = e0 * __shfl_up_sync(FULL, pc, 1);
    float xu0 = fmaf(S_C, xe, xl0),                  pu0 = fmaf(S_C, pe, pl0);
    float xu1 = fmaf(0.5f, xe, xl1),                 pu1 = fmaf(0.5f, pe, pl1);
    float xu2 = fmaf(0.35355339059327373f, xe, xl2), pu2 = fmaf(0.35355339059327373f, pe, pl2);
    float xu3 = fmaf(0.25f, xe, xl3),                pu3 = fmaf(0.25f, pe, pl3);
    float xtn = __shfl_down_sync(FULL, x[0], 1);
    float ptn = __shfl_down_sync(FULL, p[0], 1);
    x[0] = S_C * (xu0 - x[1]);   p[0] = S_C * (pu0 - p[1]);
    x[1] = S_C * (xu1 - x[2]);   p[1] = S_C * (pu1 - p[2]);
    x[2] = S_C * (xu2 - x[3]);   p[2] = S_C * (pu2 - p[3]);
    x[3] = s31 * (xu3 - m31 * xtn);
    p[3] = s31 * (pu3 - m31 * ptn);
}

// ---------------------------------------------------------------------------
// GEMM helpers
// ---------------------------------------------------------------------------
__device__ __forceinline__ void ldsm_x4(unsigned addr, unsigned& r0, unsigned& r1,
                                        unsigned& r2, unsigned& r3)
{
    asm volatile("ldmatrix.sync.aligned.m8n8.x4.shared.b16 {%0,%1,%2,%3}, [%4];"
                 : "=r"(r0), "=r"(r1), "=r"(r2), "=r"(r3) : "r"(addr));
}
__device__ __forceinline__ void mma_f16(float* d, const unsigned* a,
                                        unsigned b0, unsigned b1)
{
    asm volatile("mma.sync.aligned.m16n8k16.row.col.f32.f16.f16.f32 "
                 "{%0,%1,%2,%3}, {%4,%5,%6,%7}, {%8,%9}, {%0,%1,%2,%3};"
                 : "+f"(d[0]), "+f"(d[1]), "+f"(d[2]), "+f"(d[3])
                 : "r"(a[0]), "r"(a[1]), "r"(a[2]), "r"(a[3]), "r"(b0), "r"(b1));
}

__device__ __forceinline__ void load_A(float4 pf[8], const float* __restrict__ x,
                                       int tile, int tid)
{
    size_t m0 = (size_t)tile * M_TILE;
#pragma unroll
    for (int it = 0; it < 4; ++it) {
        int idx = tid + it * NTHREADS;            // 0..1023
        int rr = idx >> 4, cc = idx & 15;
        const float4* g = (const float4*)(x + (m0 + rr) * NMODES + cc * 8);
        pf[2 * it]     = __ldg(g);
        pf[2 * it + 1] = __ldg(g + 1);
    }
}

__device__ __forceinline__ void convert_A(char* smem, unsigned offA,
                                          const float4 pf[8], int tid)
{
#pragma unroll
    for (int it = 0; it < 4; ++it) {
        int idx = tid + it * NTHREADS;
        int rr = idx >> 4, cc = idx & 15;
        float vs[8] = {pf[2*it].x, pf[2*it].y, pf[2*it].z, pf[2*it].w,
                       pf[2*it+1].x, pf[2*it+1].y, pf[2*it+1].z, pf[2*it+1].w};
        unsigned h[4];
#pragma unroll
        for (int k = 0; k < 4; ++k)
            asm("cvt.rn.f16x2.f32 %0, %1, %2;"
                : "=r"(h[k]) : "f"(vs[2 * k + 1]), "f"(vs[2 * k]));
        unsigned off = rr * 256 + ((cc ^ (rr & 7)) << 4);
        *(uint4*)(smem + offA + off) = make_uint4(h[0], h[1], h[2], h[3]);
    }
}

// ---------------------------------------------------------------------------
// Fused kernel: phase A (CTAs 0..31 build W) | grid barrier | phase B (GEMM)
// ---------------------------------------------------------------------------
__global__ __launch_bounds__(NTHREADS, 2) void fused_kernel(
    const float* __restrict__ x,
    const float* __restrict__ params,
    float* __restrict__ out)
{
    extern __shared__ char smem[];
    const unsigned sbase = (unsigned)__cvta_generic_to_shared(smem);
    __shared__ float c_s[64];
    int tid = threadIdx.x, lane = tid & 31, wid = tid >> 5;
    int cta = blockIdx.x;
    const int q = cta & 1;

    // ---- everyone: issue first A-tile loads (overlaps phase A) ----
    int t = cta >> 1;                           // 0..147
    float4 pf[8];
    load_A(pf, x, t, tid);

    // ================= phase A: build W (CTAs 0..31) =================
    if (cta < 32) {
        float4* sblk  = (float4*)(smem + OFF_A);            // 16 KB
        float*  wpart = (float*)(smem + OFF_A + 16384);     // 4 KB
#pragma unroll
        for (int q4 = 0; q4 < 4; ++q4) {
            int idx = tid + q4 * 256;
            int l = idx >> 7, b = idx & 127;
            float th1 = params[l * (3 * NMODES) + 3 * b + 0];
            float r   = params[l * (3 * NMODES) + 3 * b + 1];
            float th2 = params[l * (3 * NMODES) + 3 * b + 2];
            float s1, c1, s2, c2;
            __sincosf(th1, &s1, &c1);
            __sincosf(th2, &s2, &c2);
            float em = __expf(-r), ep = __expf(r);
            float A00 =  em * c1, A01 = -em * s1;
            float A10 =  ep * s1, A11 =  ep * c1;
            sblk[idx] = make_float4(c2 * A00 - s2 * A10,
                                    c2 * A01 - s2 * A11,
                                    s2 * A00 + c2 * A10,
                                    s2 * A01 + c2 * A11);
        }
        __syncthreads();

        int c = cta * 8 + wid;                  // S column 0..255
        float a0   = (lane == 0)  ? 1.f : S_C;
        float c1m  = (lane >= 1)  ? 0.25f : 0.f;
        float c2m  = (lane >= 2)  ? 0.0625f : 0.f;
        float c4m  = (lane >= 4)  ? 0.00390625f : 0.f;
        float c8m  = (lane >= 8)  ? 1.52587890625e-05f : 0.f;
        float c16m = (lane >= 16) ? 2.3283064365386963e-10f : 0.f;
        float e0   = (lane == 0)  ? 0.f : 1.f;
        float s31  = (lane == 31) ? 1.f : S_C;
        float m31  = (lane == 31) ? 0.f : 1.f;

        float xx[4], pp[4];
#pragma unroll
        for (int j = 0; j < 4; ++j) {
            int b = 4 * lane + j;
            xx[j] = (c == 2 * b)     ? 1.f : 0.f;
            pp[j] = (c == 2 * b + 1) ? 1.f : 0.f;
        }
        for (int l = 0; l < NLAYERS; ++l) {
#pragma unroll
            for (int j = 0; j < 4; ++j) {
                float4 Bv = sblk[l * NMODES + 4 * lane + j];
                float nx = Bv.x * xx[j] + Bv.y * pp[j];
                float np = Bv.z * xx[j] + Bv.w * pp[j];
                xx[j] = nx; pp[j] = np;
            }
            bs_chain2(xx, pp, a0, c1m, c2m, c4m, c8m, c16m, e0, s31, m31);
        }

        // even S-columns are W columns: write fp16 hi/lo directly
        if ((wid & 1) == 0) {
            int k = c >> 1;
#pragma unroll
            for (int j = 0; j < 4; ++j) {
                int b = 4 * lane + j;
                float wx = xx[j] * WSCALE;
                float wp = pp[j] * WSCALE;
                __half hx = __float2half_rn(wx);
                __half hp = __float2half_rn(wp);
                g_Wh[(2 * b)     * NMODES + k] = hx;
                g_Wh[(2 * b + 1) * NMODES + k] = hp;
                g_Wl[(2 * b)     * NMODES + k] = __float2half_rn(wx - __half2float(hx));
                g_Wl[(2 * b + 1) * NMODES + k] = __float2half_rn(wp - __half2float(hp));
            }
        }
        // row-square partials (all columns contribute)
#pragma unroll
        for (int j = 0; j < 4; ++j)
            wpart[wid * NMODES + 4 * lane + j] = xx[j] * xx[j] + pp[j] * pp[j];
        __syncthreads();
        if (tid < NMODES) {
            float s = 0.f;
#pragma unroll
            for (int w = 0; w < 8; ++w) s += wpart[w * NMODES + tid];
            g_part[cta * NMODES + tid] = s;
        }
    }

    // ================= grid barrier (epoch-based, replay-safe) =================
    __threadfence();
    __syncthreads();
    if (tid == 0) {
        unsigned v = atomicAdd(&g_bar, 1u);
        unsigned target = v - (v % (unsigned)GRID_P) + (unsigned)GRID_P;
        for (;;) {
            unsigned cur;
            asm volatile("ld.global.acquire.gpu.u32 %0, [%1];"
                         : "=r"(cur) : "l"(&g_bar));
            if (cur >= target) break;
            __nanosleep(128);
        }
    }
    __syncthreads();
    __threadfence();

    // ================= phase B: persistent GEMM =================
    int wm = wid & 1;          // 2 m-groups x 32 rows
    int wn = wid >> 1;         // 4 n-groups x 32 smem rows (16 modes)

    // stage this half's W (hi+lo) with N-permutation, swizzled
#pragma unroll
    for (int it = 0; it < 16; ++it) {
        int idx = tid + it * NTHREADS;           // 0..4095 units of 16B
        int arr = idx >> 11;
        int rem = idx & 2047;
        int rr  = rem >> 4;
        int cc  = idx & 15;
        int g   = rr >> 5, p = rr & 31;
        int ntj = p >> 3, cx = (p >> 1) & 3, par = p & 1;
        int ml  = cx * 4 + ntj;
        int j   = q * 128 + g * 32 + 2 * ml + par;
        uint4 v = *(const uint4*)((arr ? g_Wl : g_Wh) + j * NMODES + cc * 8);
        *(uint4*)(smem + (arr ? OFF_WL : OFF_WH) + rr * 256 + ((cc ^ (rr & 7)) << 4)) = v;
    }

    // per-mode constants for this half
    if (tid < 64) {
        float s = 0.f;
#pragma unroll
        for (int cb = 0; cb < 32; ++cb)
            s += g_part[cb * NMODES + q * 64 + tid];
        c_s[tid] = 0.25f * s - 0.5f;
    }

    // ldsm lane mappings
    int a_row = (lane & 15);
    int a_cc  = (lane >> 4);
    int b_row = ((lane >> 4) << 3) + (lane & 7);
    int b_cc  = ((lane >> 3) & 1);

    const unsigned WhB = sbase + OFF_WH;
    const unsigned WlB = sbase + OFF_WL;

    // prologue: convert first tile, prefetch second
    convert_A(smem, OFF_A, pf, tid);
    if (t + STRIDE_T < NTILES_M) load_A(pf, x, t + STRIDE_T, tid);
    __syncthreads();

    float cvals[4];
#pragma unroll
    for (int j = 0; j < 4; ++j)
        cvals[j] = c_s[wn * 16 + (lane & 3) * 4 + j];

    int buf = 0;
    while (t < NTILES_M) {
        float acc[2][4][4];
#pragma unroll
        for (int mf = 0; mf < 2; ++mf)
#pragma unroll
            for (int j = 0; j < 4; ++j)
#pragma unroll
                for (int v = 0; v < 4; ++v) acc[mf][j][v] = 0.f;

        unsigned AB = sbase + OFF_A + buf * 16384;
#pragma unroll
        for (int ks = 0; ks < 8; ++ks) {
            unsigned af[2][4];
#pragma unroll
            for (int mf = 0; mf < 2; ++mf) {
                int ar = wm * 32 + mf * 16 + a_row;
                int cc = 2 * ks + a_cc;
                ldsm_x4(AB + ar * 256 + ((cc ^ (ar & 7)) << 4),
                        af[mf][0], af[mf][1], af[mf][2], af[mf][3]);
            }
            unsigned bh[2][4], bl[2][4];
#pragma unroll
            for (int p = 0; p < 2; ++p) {
                int br = wn * 32 + p * 16 + b_row;
                int cc = 2 * ks + b_cc;
                unsigned soff = br * 256 + ((cc ^ (br & 7)) << 4);
                ldsm_x4(WhB + soff, bh[p][0], bh[p][1], bh[p][2], bh[p][3]);
                ldsm_x4(WlB + soff, bl[p][0], bl[p][1], bl[p][2], bl[p][3]);
            }
#pragma unroll
            for (int p = 0; p < 2; ++p) {
                mma_f16(acc[0][2*p],   af[0], bh[p][0], bh[p][1]);
                mma_f16(acc[1][2*p],   af[1], bh[p][0], bh[p][1]);
                mma_f16(acc[0][2*p+1], af[0], bh[p][2], bh[p][3]);
                mma_f16(acc[1][2*p+1], af[1], bh[p][2], bh[p][3]);
            }
#pragma unroll
            for (int p = 0; p < 2; ++p) {
                mma_f16(acc[0][2*p],   af[0], bl[p][0], bl[p][1]);
                mma_f16(acc[1][2*p],   af[1], bl[p][0], bl[p][1]);
                mma_f16(acc[0][2*p+1], af[0], bl[p][2], bl[p][3]);
                mma_f16(acc[1][2*p+1], af[1], bl[p][2], bl[p][3]);
            }
        }

        // convert next tile into other A buffer (disjoint; no barrier)
        if (t + STRIDE_T < NTILES_M)
            convert_A(smem, OFF_A + (buf ^ 1) * 16384, pf, tid);

        // epilogue: dense STG.128 from registers (undo 1/16 W scale)
        {
            size_t m0 = (size_t)t * M_TILE;
            int mode0 = q * 64 + wn * 16 + (lane & 3) * 4;
#pragma unroll
            for (int mf = 0; mf < 2; ++mf) {
#pragma unroll
                for (int h = 0; h < 2; ++h) {
                    int row = wm * 32 + mf * 16 + (lane >> 2) + h * 8;
                    float* o = out + (m0 + row) * NMODES + mode0;
                    float v[4];
#pragma unroll
                    for (int j = 0; j < 4; ++j) {
                        float f0 = acc[mf][j][2 * h]     * WSCALE_INV;
                        float f1 = acc[mf][j][2 * h + 1] * WSCALE_INV;
                        v[j] = fmaf(f0, f0, fmaf(f1, f1, cvals[j]));
                    }
                    *(float4*)o = make_float4(v[0], v[1], v[2], v[3]);
                }
            }
        }

        // prefetch tile t+2*stride
        if (t + 2 * STRIDE_T < NTILES_M) load_A(pf, x, t + 2 * STRIDE_T, tid);

        __syncthreads();           // converts visible before next MMA loop
        t += STRIDE_T;
        buf ^= 1;
    }
}

// ---------------------------------------------------------------------------
// Launch
// ---------------------------------------------------------------------------
extern "C" void kernel_launch(void* const* d_in, const int* in_sizes, int n_in,
                              void* d_out, int out_size)
{
    const float* inputs = (const float*)d_in[0];
    const float* params = (const float*)d_in[1];
    float* out = (float*)d_out;

    cudaFuncSetAttribute(fused_kernel, cudaFuncAttributeMaxDynamicSharedMemorySize,
                         SMEM_BYTES);

    fused_kernel<<<GRID_P, NTHREADS, SMEM_BYTES>>>(inputs, params, out);
}